// round 1
// baseline (speedup 1.0000x reference)
#include <cuda_runtime.h>
#include <cstddef>

#define BB 2048
#define NN 128
#define DD 512

// 8 MB scratch for cw = content @ cow, rows interleaved: row 2b = text[b]@cow, 2b+1 = img[b]@cow
__device__ float g_cw[(size_t)2 * BB * DD];

// ---------------------------------------------------------------------------
// Kernel 1: cw[r][d] = sum_e A[r][e] * cow[e][d],  A row r: (r&1)? img[r>>1] : text[r>>1]
// Tiled fp32 GEMM: BM=64, BN=128, BK=16, 256 threads, 4x8 per-thread microtile.
// ---------------------------------------------------------------------------
#define GBM 64
#define GBN 128
#define GBK 16

__global__ __launch_bounds__(256) void gemm_cw_kernel(
    const float* __restrict__ text, const float* __restrict__ img,
    const float* __restrict__ cow) {
  __shared__ __align__(16) float As[GBK][GBM];
  __shared__ __align__(16) float Bs[GBK][GBN];
  const int tid = threadIdx.x;
  const int tx = tid & 15;   // 16 cols of threads, 8 outputs each -> 128
  const int ty = tid >> 4;   // 16 rows of threads, 4 outputs each -> 64
  const int m0 = blockIdx.y * GBM;
  const int n0 = blockIdx.x * GBN;

  float acc[4][8];
#pragma unroll
  for (int i = 0; i < 4; i++)
#pragma unroll
    for (int j = 0; j < 8; j++) acc[i][j] = 0.f;

  for (int kk = 0; kk < DD; kk += GBK) {
    // Load A tile: 64 rows x 16 cols = 256 float4, one per thread.
    {
      const int row = tid >> 2;
      const int c4 = tid & 3;
      const int r = m0 + row;
      const float* src = ((r & 1) ? img : text) + (size_t)(r >> 1) * DD + kk + c4 * 4;
      float4 v = *(const float4*)src;
      As[c4 * 4 + 0][row] = v.x;
      As[c4 * 4 + 1][row] = v.y;
      As[c4 * 4 + 2][row] = v.z;
      As[c4 * 4 + 3][row] = v.w;
    }
    // Load B tile: 16 rows x 128 cols = 512 float4, two per thread.
#pragma unroll
    for (int i = 0; i < 2; i++) {
      const int f = tid + i * 256;
      const int row = f >> 5;
      const int c4 = f & 31;
      *(float4*)&Bs[row][c4 * 4] =
          *(const float4*)(cow + (size_t)(kk + row) * DD + n0 + c4 * 4);
    }
    __syncthreads();

#pragma unroll
    for (int k = 0; k < GBK; k++) {
      float4 av = *(const float4*)&As[k][ty * 4];
      float4 b0 = *(const float4*)&Bs[k][tx * 8];
      float4 b1 = *(const float4*)&Bs[k][tx * 8 + 4];
      float a_[4] = {av.x, av.y, av.z, av.w};
      float b_[8] = {b0.x, b0.y, b0.z, b0.w, b1.x, b1.y, b1.z, b1.w};
#pragma unroll
      for (int i = 0; i < 4; i++)
#pragma unroll
        for (int j = 0; j < 8; j++) acc[i][j] = fmaf(a_[i], b_[j], acc[i][j]);
    }
    __syncthreads();
  }

#pragma unroll
  for (int i = 0; i < 4; i++) {
    const int r = m0 + ty * 4 + i;
    float4 o0 = make_float4(acc[i][0], acc[i][1], acc[i][2], acc[i][3]);
    float4 o1 = make_float4(acc[i][4], acc[i][5], acc[i][6], acc[i][7]);
    *(float4*)&g_cw[(size_t)r * DD + n0 + tx * 8] = o0;
    *(float4*)&g_cw[(size_t)r * DD + n0 + tx * 8 + 4] = o1;
  }
}

// ---------------------------------------------------------------------------
// Kernel 2: fused co-attention. One CTA per sample, 8 warps, warp-per-comment,
// single streaming pass over comment with online softmax (flash-style).
// ---------------------------------------------------------------------------
__device__ __forceinline__ float tanh_fast(float x) {
  float y;
  asm("tanh.approx.f32 %0, %1;" : "=f"(y) : "f"(x));
  return y;
}

__global__ __launch_bounds__(256, 2) void fusion_kernel(
    const float* __restrict__ text, const float* __restrict__ img,
    const float* __restrict__ comment, const int* __restrict__ cnum,
    const float* __restrict__ W_ca, const float* __restrict__ b_ca,
    const float* __restrict__ W_co, const float* __restrict__ b_co,
    float* __restrict__ out) {
  const int b = blockIdx.x;
  const int tid = threadIdx.x;
  const int wid = tid >> 5;
  const int lane = tid & 31;

  __shared__ __align__(16) float s_c0[DD], s_c1[DD], s_wca[DD], s_wco[DD];
  __shared__ __align__(16) float s_acc0[DD], s_acc1[DD], s_accz[DD];
  __shared__ float s_m[8], s_s[8], s_r0[8], s_r1[8];

  for (int i = tid; i < DD; i += 256) {
    s_c0[i] = text[(size_t)b * DD + i];
    s_c1[i] = img[(size_t)b * DD + i];
    s_wca[i] = W_ca[i];
    s_wco[i] = W_co[i];
    s_acc0[i] = 0.f;
    s_acc1[i] = 0.f;
    s_accz[i] = 0.f;
  }
  const int cnt = cnum[b];
  const float bca = b_ca[0], bco = b_co[0];
  __syncthreads();

  // Register-resident cw rows for this sample (lane covers d = 4*lane + 128*j + c)
  float4 cw0r[4], cw1r[4];
  {
    const float4* p0 = (const float4*)(g_cw + (size_t)(2 * b) * DD);
    const float4* p1 = (const float4*)(g_cw + (size_t)(2 * b + 1) * DD);
#pragma unroll
    for (int j = 0; j < 4; j++) {
      cw0r[j] = p0[lane + 32 * j];
      cw1r[j] = p1[lane + 32 * j];
    }
  }

  const float4* c04 = (const float4*)s_c0;
  const float4* c14 = (const float4*)s_c1;
  const float4* wco4 = (const float4*)s_wco;

  float mrun = -INFINITY, ssum = 0.f;
  float4 azr[4], a0r[4], a1r[4];
#pragma unroll
  for (int j = 0; j < 4; j++) {
    azr[j] = make_float4(0.f, 0.f, 0.f, 0.f);
    a0r[j] = make_float4(0.f, 0.f, 0.f, 0.f);
    a1r[j] = make_float4(0.f, 0.f, 0.f, 0.f);
  }

  for (int n = wid; n < cnt; n += 8) {
    const float4* zp = (const float4*)(comment + ((size_t)b * NN + n) * DD);
    float4 zv[4];
#pragma unroll
    for (int j = 0; j < 4; j++) zv[j] = zp[lane + 32 * j];

    // co_w dots: s_k = cw_k . z[n]
    float s0 = 0.f, s1 = 0.f;
#pragma unroll
    for (int j = 0; j < 4; j++) {
      s0 += zv[j].x * cw0r[j].x + zv[j].y * cw0r[j].y + zv[j].z * cw0r[j].z + zv[j].w * cw0r[j].w;
      s1 += zv[j].x * cw1r[j].x + zv[j].y * cw1r[j].y + zv[j].z * cw1r[j].z + zv[j].w * cw1r[j].w;
    }
#pragma unroll
    for (int off = 16; off > 0; off >>= 1) {
      s0 += __shfl_xor_sync(0xffffffffu, s0, off);
      s1 += __shfl_xor_sync(0xffffffffu, s1, off);
    }
    const float w0 = tanh_fast(s0);
    const float w1 = tanh_fast(s1);

    // zw logit: W_co . tanh(z + w0*c0 + w1*c1)
    float pz = 0.f;
#pragma unroll
    for (int j = 0; j < 4; j++) {
      float4 c0v = c04[lane + 32 * j];
      float4 c1v = c14[lane + 32 * j];
      float4 wv = wco4[lane + 32 * j];
      pz += wv.x * tanh_fast(zv[j].x + w0 * c0v.x + w1 * c1v.x);
      pz += wv.y * tanh_fast(zv[j].y + w0 * c0v.y + w1 * c1v.y);
      pz += wv.z * tanh_fast(zv[j].z + w0 * c0v.z + w1 * c1v.z);
      pz += wv.w * tanh_fast(zv[j].w + w0 * c0v.w + w1 * c1v.w);
    }
#pragma unroll
    for (int off = 16; off > 0; off >>= 1) pz += __shfl_xor_sync(0xffffffffu, pz, off);
    const float l = pz + bco;

    // online softmax update (warp-uniform l)
    const float mnew = fmaxf(mrun, l);
    const float fac = __expf(mrun - mnew);  // -inf first time -> 0
    const float pe = __expf(l - mnew);
    ssum = ssum * fac + pe;
    if (fac != 1.f) {
#pragma unroll
      for (int j = 0; j < 4; j++) {
        azr[j].x *= fac; azr[j].y *= fac; azr[j].z *= fac; azr[j].w *= fac;
      }
    }
#pragma unroll
    for (int j = 0; j < 4; j++) {
      azr[j].x += pe * zv[j].x; azr[j].y += pe * zv[j].y;
      azr[j].z += pe * zv[j].z; azr[j].w += pe * zv[j].w;
      a0r[j].x += w0 * zv[j].x; a0r[j].y += w0 * zv[j].y;
      a0r[j].z += w0 * zv[j].z; a0r[j].w += w0 * zv[j].w;
      a1r[j].x += w1 * zv[j].x; a1r[j].y += w1 * zv[j].y;
      a1r[j].z += w1 * zv[j].z; a1r[j].w += w1 * zv[j].w;
    }
    mrun = mnew;
  }

  if (lane == 0) { s_m[wid] = mrun; s_s[wid] = ssum; }
  __syncthreads();

  float M = s_m[0];
#pragma unroll
  for (int w = 1; w < 8; w++) M = fmaxf(M, s_m[w]);
  float S = 0.f;
#pragma unroll
  for (int w = 0; w < 8; w++) S += s_s[w] * __expf(s_m[w] - M);
  const float rsc = __expf(mrun - M);  // this warp's rescale (0 if warp had no n)

  // deterministic serialized merge of per-warp accumulators into smem
  float4* acc04 = (float4*)s_acc0;
  float4* acc14 = (float4*)s_acc1;
  float4* accz4 = (float4*)s_accz;
  for (int w = 0; w < 8; w++) {
    if (wid == w) {
#pragma unroll
      for (int j = 0; j < 4; j++) {
        const int idx = lane + 32 * j;
        float4 t0 = acc04[idx];
        t0.x += a0r[j].x; t0.y += a0r[j].y; t0.z += a0r[j].z; t0.w += a0r[j].w;
        acc04[idx] = t0;
        float4 t1 = acc14[idx];
        t1.x += a1r[j].x; t1.y += a1r[j].y; t1.z += a1r[j].z; t1.w += a1r[j].w;
        acc14[idx] = t1;
        float4 tz = accz4[idx];
        tz.x += rsc * azr[j].x; tz.y += rsc * azr[j].y;
        tz.z += rsc * azr[j].z; tz.w += rsc * azr[j].w;
        accz4[idx] = tz;
      }
    }
    __syncthreads();
  }

  // content attention logits + softmax over the 2 content rows
  float p0 = 0.f, p1 = 0.f;
  for (int i = tid; i < DD; i += 256) {
    p0 += s_wca[i] * tanh_fast(s_c0[i] + s_acc0[i]);
    p1 += s_wca[i] * tanh_fast(s_c1[i] + s_acc1[i]);
  }
#pragma unroll
  for (int off = 16; off > 0; off >>= 1) {
    p0 += __shfl_xor_sync(0xffffffffu, p0, off);
    p1 += __shfl_xor_sync(0xffffffffu, p1, off);
  }
  if (lane == 0) { s_r0[wid] = p0; s_r1[wid] = p1; }
  __syncthreads();
  float l0 = bca, l1 = bca;
#pragma unroll
  for (int w = 0; w < 8; w++) { l0 += s_r0[w]; l1 += s_r1[w]; }
  const float mx = fmaxf(l0, l1);
  const float e0 = __expf(l0 - mx);
  const float e1 = __expf(l1 - mx);
  const float inv2 = 1.f / (e0 + e1);
  const float cwt0 = e0 * inv2;
  const float cwt1 = e1 * inv2;

  float* out_rc = out;
  float* out_rcm = out + (size_t)BB * DD;
  float* out_cw = out + (size_t)2 * BB * DD;
  if (tid == 0) {
    out_cw[2 * b] = cwt0;
    out_cw[2 * b + 1] = cwt1;
  }
  const float invS = 1.f / S;
  for (int i = tid; i < DD; i += 256) {
    out_rc[(size_t)b * DD + i] = s_c0[i] * cwt0 + s_c1[i] * cwt1;
    out_rcm[(size_t)b * DD + i] = s_accz[i] * invS;
  }
}

// ---------------------------------------------------------------------------
extern "C" void kernel_launch(void* const* d_in, const int* in_sizes, int n_in,
                              void* d_out, int out_size) {
  const float* text = (const float*)d_in[0];
  const float* img = (const float*)d_in[1];
  const float* comment = (const float*)d_in[2];
  const int* cnum = (const int*)d_in[3];
  const float* cow = (const float*)d_in[4];
  const float* W_ca = (const float*)d_in[5];
  const float* b_ca = (const float*)d_in[6];
  const float* W_co = (const float*)d_in[7];
  const float* b_co = (const float*)d_in[8];
  float* out = (float*)d_out;

  dim3 ggrid(DD / GBN, (2 * BB) / GBM);  // (4, 64) = 256 CTAs
  gemm_cw_kernel<<<ggrid, 256>>>(text, img, cow);
  fusion_kernel<<<BB, 256>>>(text, img, comment, cnum, W_ca, b_ca, W_co, b_co, out);
}